// round 2
// baseline (speedup 1.0000x reference)
#include <cuda_runtime.h>
#include <cstdint>

// Problem constants (reference: N_NODES=100000, IN_FEAT=128)
#define NODES_MAX 100032
#define FEAT 128

// Per-node projections: R[n][0:128] = feat[n] @ A.T + b1  (A = W1[:, :128])
//                       R[n][128:256] = feat[n] @ B.T     (B = W1[:, 128:])
// 100032 * 256 * 4B ~= 102.4 MB device scratch (static, allocation-free).
__device__ float g_R[(size_t)NODES_MAX * 256];

// ---------------------------------------------------------------------------
// Kernel 1: node projection GEMM.  [n_nodes,128] x [128,256] -> g_R
// Tile: 64 nodes x 256 outputs, K=128 fully resident in shared memory.
// 256 threads, 8x8 register micro-tile per thread.
// ---------------------------------------------------------------------------
__global__ void node_gemm_kernel(const float* __restrict__ feat,
                                 const float* __restrict__ W1,
                                 const float* __restrict__ b1,
                                 int n_nodes) {
    extern __shared__ float smem[];
    float* Xs = smem;                // [64][128]   (32 KB)
    float* Ws = smem + 64 * 128;     // [128][260]  (~130 KB, padded rows)

    const int tid = threadIdx.x;
    const int block_node = blockIdx.x * 64;

    // ---- Load weights into Ws[k][o] (o in [0,256)) ----
    {
        const int o = tid;                // 0..255
        const int r = o & 127;            // W1 row
        const int half = o >> 7;          // 0 -> A cols [0,128), 1 -> B cols [128,256)
        const float4* wsrc = reinterpret_cast<const float4*>(W1) + (size_t)r * 64 + half * 32;
        #pragma unroll 8
        for (int k4 = 0; k4 < 32; ++k4) {
            float4 w = wsrc[k4];
            int k = k4 * 4;
            Ws[(k + 0) * 260 + o] = w.x;
            Ws[(k + 1) * 260 + o] = w.y;
            Ws[(k + 2) * 260 + o] = w.z;
            Ws[(k + 3) * 260 + o] = w.w;
        }
    }

    // ---- Load X tile [64][128], coalesced float4 ----
    {
        const float4* f4 = reinterpret_cast<const float4*>(feat);
        float4* x4 = reinterpret_cast<float4*>(Xs);
        #pragma unroll
        for (int t = 0; t < 8; ++t) {
            int idx4 = tid + t * 256;          // 0..2047 (64 rows x 32 float4)
            int m = idx4 >> 5;
            int node = block_node + m;
            float4 v = make_float4(0.f, 0.f, 0.f, 0.f);
            if (node < n_nodes) v = f4[(size_t)node * 32 + (idx4 & 31)];
            x4[idx4] = v;
        }
    }
    __syncthreads();

    // ---- Main loop: 8 nodes x 8 outputs per thread ----
    const int tx = tid & 31;
    const int ty = tid >> 5;
    const float* xrow = Xs + ty * 8 * 128;

    float acc[8][8];
    #pragma unroll
    for (int i = 0; i < 8; ++i)
        #pragma unroll
        for (int j = 0; j < 8; ++j) acc[i][j] = 0.f;

    #pragma unroll 4
    for (int k = 0; k < 128; ++k) {
        float4 bP = *reinterpret_cast<const float4*>(Ws + k * 260 + tx * 4);
        float4 bQ = *reinterpret_cast<const float4*>(Ws + k * 260 + 128 + tx * 4);
        #pragma unroll
        for (int i = 0; i < 8; ++i) {
            float a = xrow[i * 128 + k];
            acc[i][0] = fmaf(a, bP.x, acc[i][0]);
            acc[i][1] = fmaf(a, bP.y, acc[i][1]);
            acc[i][2] = fmaf(a, bP.z, acc[i][2]);
            acc[i][3] = fmaf(a, bP.w, acc[i][3]);
            acc[i][4] = fmaf(a, bQ.x, acc[i][4]);
            acc[i][5] = fmaf(a, bQ.y, acc[i][5]);
            acc[i][6] = fmaf(a, bQ.z, acc[i][6]);
            acc[i][7] = fmaf(a, bQ.w, acc[i][7]);
        }
    }

    // ---- Epilogue: fold b1 into P half, store float4 ----
    float4 bv = *reinterpret_cast<const float4*>(b1 + tx * 4);
    #pragma unroll
    for (int i = 0; i < 8; ++i) {
        int node = block_node + ty * 8 + i;
        if (node >= n_nodes) break;
        float* rrow = g_R + (size_t)node * 256;
        float4 p = make_float4(acc[i][0] + bv.x, acc[i][1] + bv.y,
                               acc[i][2] + bv.z, acc[i][3] + bv.w);
        float4 q = make_float4(acc[i][4], acc[i][5], acc[i][6], acc[i][7]);
        *reinterpret_cast<float4*>(rrow + tx * 4) = p;
        *reinterpret_cast<float4*>(rrow + 128 + tx * 4) = q;
    }
}

// ---------------------------------------------------------------------------
// Kernel 2: per-edge score. One warp per edge; each lane handles 4 channels.
// score[e] = W2 . relu(P[src] + Q[dst]) + b2
// NOTE: src/dst arrive as int32 (JAX x64-disabled downcasts the int64 request).
// ---------------------------------------------------------------------------
__global__ void edge_score_kernel(const int* __restrict__ src,
                                  const int* __restrict__ dst,
                                  const float* __restrict__ W2,
                                  const float* __restrict__ b2,
                                  float* __restrict__ out,
                                  int n_edges) {
    int e = (int)((blockIdx.x * (unsigned)blockDim.x + threadIdx.x) >> 5);
    int lane = threadIdx.x & 31;
    if (e >= n_edges) return;

    int s = __ldg(src + e);
    int d = __ldg(dst + e);

    const float4 p = *reinterpret_cast<const float4*>(g_R + (size_t)s * 256 + lane * 4);
    const float4 q = *reinterpret_cast<const float4*>(g_R + (size_t)d * 256 + 128 + lane * 4);
    const float4 w = __ldg(reinterpret_cast<const float4*>(W2) + lane);

    float v = fmaxf(p.x + q.x, 0.f) * w.x
            + fmaxf(p.y + q.y, 0.f) * w.y
            + fmaxf(p.z + q.z, 0.f) * w.z
            + fmaxf(p.w + q.w, 0.f) * w.w;

    #pragma unroll
    for (int off = 16; off; off >>= 1)
        v += __shfl_xor_sync(0xffffffffu, v, off);

    if (lane == 0) out[e] = v + __ldg(b2);
}

// ---------------------------------------------------------------------------
// kernel_launch — graph-capturable, allocation-free.
// Inputs (metadata order): feature[f32 N*128], src[i32 E], dst[i32 E],
//                          W1[f32 128*256], b1[f32 128], W2[f32 128], b2[f32 1]
// Output: float32 [E] (scores).
// ---------------------------------------------------------------------------
extern "C" void kernel_launch(void* const* d_in, const int* in_sizes, int n_in,
                              void* d_out, int out_size) {
    const float* feat = (const float*)d_in[0];
    const int*   src  = (const int*)d_in[1];
    const int*   dst  = (const int*)d_in[2];
    const float* W1   = (const float*)d_in[3];
    const float* b1   = (const float*)d_in[4];
    const float* W2   = (const float*)d_in[5];
    const float* b2   = (const float*)d_in[6];
    float*       out  = (float*)d_out;

    int n_nodes = in_sizes[0] / FEAT;
    int n_edges = in_sizes[1];

    const int smem_bytes = (64 * 128 + 128 * 260) * (int)sizeof(float);  // ~162 KB
    cudaFuncSetAttribute(node_gemm_kernel,
                         cudaFuncAttributeMaxDynamicSharedMemorySize, smem_bytes);

    node_gemm_kernel<<<(n_nodes + 63) / 64, 256, smem_bytes>>>(feat, W1, b1, n_nodes);
    edge_score_kernel<<<(n_edges + 7) / 8, 256>>>(src, dst, W2, b2, out, n_edges);
}

// round 3
// speedup vs baseline: 1.2746x; 1.2746x over previous
#include <cuda_runtime.h>
#include <cstdint>

#define NODES_MAX 100032
#define FEAT 128
#define XS_STRIDE 132   // 128 + 4 pad floats (keeps 16B alignment, row = 528B)
#define WS_STRIDE 260   // 256 + 4 pad floats (row = 1040B, conflict-free LDS.128)

// Per-node projections: R[n][0:128] = feat[n] @ A.T + b1, R[n][128:256] = feat[n] @ B.T
__device__ float g_R[(size_t)NODES_MAX * 256];

// Packed f32x2 FMA: acc = a2 * b2 + acc  (2 fp32 MACs per issue on sm_103a)
#define FMA2(acc, a2, b2) \
    asm("fma.rn.f32x2 %0, %1, %2, %0;" : "+d"(acc) : "d"(a2), "d"(b2))

__device__ __forceinline__ double pack_dup(float a) {
    double r;
    asm("mov.b64 %0, {%1, %1};" : "=d"(r) : "f"(a));
    return r;
}
__device__ __forceinline__ float f2lo(double d) { return __int_as_float(__double2loint(d)); }
__device__ __forceinline__ float f2hi(double d) { return __int_as_float(__double2hiint(d)); }

// ---------------------------------------------------------------------------
// Kernel 1: node projection GEMM via packed f32x2 FMA.
// Tile: 128 nodes x 256 outputs, K=128 resident. 256 threads.
// Thread (tx,ty): 16 nodes (ty*16..), 8 outputs (tx*4..+3 of P and of Q),
// accumulated as f32x2 output-pairs (B operand = double2 straight from smem).
// ---------------------------------------------------------------------------
__global__ void __launch_bounds__(256, 1)
node_gemm_kernel(const float* __restrict__ feat,
                 const float* __restrict__ W1,
                 const float* __restrict__ b1,
                 int n_nodes) {
    extern __shared__ float smem[];
    float* Xs = smem;                        // [128][XS_STRIDE]  ~67.6 KB
    float* Ws = smem + 128 * XS_STRIDE;      // [128][WS_STRIDE]  ~133 KB

    const int tid = threadIdx.x;
    const int block_node = blockIdx.x * 128;

    // ---- Weights -> Ws[k][o]; thread owns output column o = tid ----
    {
        const int o = tid;
        const int r = o & 127;
        const int half = o >> 7;
        const float4* wsrc = reinterpret_cast<const float4*>(W1) + (size_t)r * 64 + half * 32;
        #pragma unroll 8
        for (int k4 = 0; k4 < 32; ++k4) {
            float4 w = wsrc[k4];
            int k = k4 * 4;
            Ws[(k + 0) * WS_STRIDE + o] = w.x;
            Ws[(k + 1) * WS_STRIDE + o] = w.y;
            Ws[(k + 2) * WS_STRIDE + o] = w.z;
            Ws[(k + 3) * WS_STRIDE + o] = w.w;
        }
    }

    // ---- X tile [128 nodes][128 k], coalesced float4 ----
    {
        const float4* f4 = reinterpret_cast<const float4*>(feat);
        #pragma unroll
        for (int t = 0; t < 16; ++t) {
            int idx4 = tid + t * 256;              // 0..4095
            int m = idx4 >> 5;
            int kk = idx4 & 31;
            int node = block_node + m;
            float4 v = make_float4(0.f, 0.f, 0.f, 0.f);
            if (node < n_nodes) v = f4[(size_t)node * 32 + kk];
            *reinterpret_cast<float4*>(Xs + m * XS_STRIDE + kk * 4) = v;
        }
    }
    __syncthreads();

    const int tx = tid & 31;
    const int ty = tid >> 5;
    const float* xrow = Xs + ty * 16 * XS_STRIDE;

    // acc[i][j]: node i (of 16), output-pair j: j0,j1 = P pairs, j2,j3 = Q pairs
    double acc[16][4];
    #pragma unroll
    for (int i = 0; i < 16; ++i)
        #pragma unroll
        for (int j = 0; j < 4; ++j) acc[i][j] = 0.0;

    #pragma unroll 2
    for (int k0 = 0; k0 < 128; k0 += 4) {
        #pragma unroll
        for (int h = 0; h < 2; ++h) {               // two 8-node halves (reg pressure)
            float4 a4[8];
            #pragma unroll
            for (int i = 0; i < 8; ++i)
                a4[i] = *reinterpret_cast<const float4*>(xrow + (h * 8 + i) * XS_STRIDE + k0);
            #pragma unroll
            for (int kk = 0; kk < 4; ++kk) {
                const double2 bp = *reinterpret_cast<const double2*>(Ws + (k0 + kk) * WS_STRIDE + tx * 4);
                const double2 bq = *reinterpret_cast<const double2*>(Ws + (k0 + kk) * WS_STRIDE + 128 + tx * 4);
                #pragma unroll
                for (int i = 0; i < 8; ++i) {
                    float a = (kk == 0) ? a4[i].x : (kk == 1) ? a4[i].y
                            : (kk == 2) ? a4[i].z : a4[i].w;
                    double a2 = pack_dup(a);
                    int n = h * 8 + i;
                    FMA2(acc[n][0], a2, bp.x);
                    FMA2(acc[n][1], a2, bp.y);
                    FMA2(acc[n][2], a2, bq.x);
                    FMA2(acc[n][3], a2, bq.y);
                }
            }
        }
    }

    // ---- Epilogue: unpack pairs, fold b1 into P half ----
    float4 bv = *reinterpret_cast<const float4*>(b1 + tx * 4);
    #pragma unroll
    for (int i = 0; i < 16; ++i) {
        int node = block_node + ty * 16 + i;
        if (node >= n_nodes) break;
        float* rrow = g_R + (size_t)node * 256;
        float4 p = make_float4(f2lo(acc[i][0]) + bv.x, f2hi(acc[i][0]) + bv.y,
                               f2lo(acc[i][1]) + bv.z, f2hi(acc[i][1]) + bv.w);
        float4 q = make_float4(f2lo(acc[i][2]), f2hi(acc[i][2]),
                               f2lo(acc[i][3]), f2hi(acc[i][3]));
        *reinterpret_cast<float4*>(rrow + tx * 4) = p;
        *reinterpret_cast<float4*>(rrow + 128 + tx * 4) = q;
    }
}

// ---------------------------------------------------------------------------
// Kernel 2: per-edge score, 8 edges per warp (16 independent 512B gathers in
// flight -> hides DRAM latency). score[e] = W2 . relu(P[src]+Q[dst]) + b2
// ---------------------------------------------------------------------------
#define EPW 8
__global__ void edge_score_kernel(const int* __restrict__ src,
                                  const int* __restrict__ dst,
                                  const float* __restrict__ W2,
                                  const float* __restrict__ b2,
                                  float* __restrict__ out,
                                  int n_edges) {
    int warp = (int)((blockIdx.x * (unsigned)blockDim.x + threadIdx.x) >> 5);
    int lane = threadIdx.x & 31;
    int e0 = warp * EPW;
    if (e0 >= n_edges) return;

    const float4 w = __ldg(reinterpret_cast<const float4*>(W2) + lane);

    int si[EPW], di[EPW];
    #pragma unroll
    for (int j = 0; j < EPW; ++j) {
        int e = min(e0 + j, n_edges - 1);
        si[j] = __ldg(src + e);
        di[j] = __ldg(dst + e);
    }

    float4 p[EPW], q[EPW];
    #pragma unroll
    for (int j = 0; j < EPW; ++j)
        p[j] = *reinterpret_cast<const float4*>(g_R + (size_t)si[j] * 256 + lane * 4);
    #pragma unroll
    for (int j = 0; j < EPW; ++j)
        q[j] = *reinterpret_cast<const float4*>(g_R + (size_t)di[j] * 256 + 128 + lane * 4);

    float v[EPW];
    #pragma unroll
    for (int j = 0; j < EPW; ++j) {
        v[j] = fmaxf(p[j].x + q[j].x, 0.f) * w.x
             + fmaxf(p[j].y + q[j].y, 0.f) * w.y
             + fmaxf(p[j].z + q[j].z, 0.f) * w.z
             + fmaxf(p[j].w + q[j].w, 0.f) * w.w;
    }

    #pragma unroll
    for (int off = 16; off; off >>= 1)
        #pragma unroll
        for (int j = 0; j < EPW; ++j)
            v[j] += __shfl_xor_sync(0xffffffffu, v[j], off);

    if (lane == 0) {
        float bias = __ldg(b2);
        if (e0 + EPW <= n_edges) {
            float4 o0 = make_float4(v[0] + bias, v[1] + bias, v[2] + bias, v[3] + bias);
            float4 o1 = make_float4(v[4] + bias, v[5] + bias, v[6] + bias, v[7] + bias);
            *reinterpret_cast<float4*>(out + e0) = o0;
            *reinterpret_cast<float4*>(out + e0 + 4) = o1;
        } else {
            for (int j = 0; j < n_edges - e0; ++j) out[e0 + j] = v[j] + bias;
        }
    }
}

// ---------------------------------------------------------------------------
// kernel_launch — graph-capturable, allocation-free.
// Inputs: feature[f32 N*128], src[i32 E], dst[i32 E],
//         W1[f32 128*256], b1[f32 128], W2[f32 128], b2[f32 1]
// ---------------------------------------------------------------------------
extern "C" void kernel_launch(void* const* d_in, const int* in_sizes, int n_in,
                              void* d_out, int out_size) {
    const float* feat = (const float*)d_in[0];
    const int*   src  = (const int*)d_in[1];
    const int*   dst  = (const int*)d_in[2];
    const float* W1   = (const float*)d_in[3];
    const float* b1   = (const float*)d_in[4];
    const float* W2   = (const float*)d_in[5];
    const float* b2   = (const float*)d_in[6];
    float*       out  = (float*)d_out;

    int n_nodes = in_sizes[0] / FEAT;
    int n_edges = in_sizes[1];

    const int smem_bytes = (128 * XS_STRIDE + 128 * WS_STRIDE) * (int)sizeof(float); // ~196 KB
    cudaFuncSetAttribute(node_gemm_kernel,
                         cudaFuncAttributeMaxDynamicSharedMemorySize, smem_bytes);

    node_gemm_kernel<<<(n_nodes + 127) / 128, 256, smem_bytes>>>(feat, W1, b1, n_nodes);

    int warps = (n_edges + EPW - 1) / EPW;
    int blocks = (warps * 32 + 255) / 256;
    edge_score_kernel<<<blocks, 256>>>(src, dst, W2, b2, out, n_edges);
}

// round 5
// speedup vs baseline: 1.7864x; 1.4015x over previous
#include <cuda_runtime.h>
#include <cuda_bf16.h>
#include <cstdint>

#define NODES_MAX 100032
#define FEAT 128
#define BSTRIDE 136   // bf16 elems per smem row (128 + 8 pad -> 272B, ldmatrix conflict-free)

// Per-node projections: R[n][0:128]=relu-input P+b1 part... (bias folded here):
// R[n][o<128] = feat[n]@W1[o][0:128].T + b1[o],  R[n][128+j] = feat[n]@W1[j][128:256].T
__device__ float g_R[(size_t)NODES_MAX * 256];

// smem offsets in bf16 elements
#define OFF_AHI 0
#define OFF_ALO (128 * BSTRIDE)
#define OFF_BHI (256 * BSTRIDE)
#define OFF_BLO (512 * BSTRIDE)
#define SMEM_ELEMS (768 * BSTRIDE)              // 104448 elems = 208896 B

__device__ __forceinline__ uint32_t smem_u32(const void* p) {
    uint32_t a;
    asm("{ .reg .u64 t; cvta.to.shared.u64 t, %1; cvt.u32.u64 %0, t; }" : "=r"(a) : "l"(p));
    return a;
}
__device__ __forceinline__ void ldsm_x4(uint32_t* r, uint32_t addr) {
    asm volatile("ldmatrix.sync.aligned.m8n8.x4.shared.b16 {%0,%1,%2,%3}, [%4];"
                 : "=r"(r[0]), "=r"(r[1]), "=r"(r[2]), "=r"(r[3]) : "r"(addr));
}
__device__ __forceinline__ void mma_bf16(float* d, const uint32_t* a, const uint32_t* b) {
    asm volatile("mma.sync.aligned.m16n8k16.row.col.f32.bf16.bf16.f32 "
                 "{%0,%1,%2,%3}, {%4,%5,%6,%7}, {%8,%9}, {%0,%1,%2,%3};"
                 : "+f"(d[0]), "+f"(d[1]), "+f"(d[2]), "+f"(d[3])
                 : "r"(a[0]), "r"(a[1]), "r"(a[2]), "r"(a[3]), "r"(b[0]), "r"(b[1]));
}
__device__ __forceinline__ uint32_t pack_hi(float x, float y) {
    __nv_bfloat16 h0 = __float2bfloat16(x), h1 = __float2bfloat16(y);
    return (uint32_t)__bfloat16_as_ushort(h0) | ((uint32_t)__bfloat16_as_ushort(h1) << 16);
}
__device__ __forceinline__ uint32_t pack_lo(float x, float y) {
    __nv_bfloat16 h0 = __float2bfloat16(x), h1 = __float2bfloat16(y);
    __nv_bfloat16 l0 = __float2bfloat16(x - __bfloat162float(h0));
    __nv_bfloat16 l1 = __float2bfloat16(y - __bfloat162float(h1));
    return (uint32_t)__bfloat16_as_ushort(l0) | ((uint32_t)__bfloat16_as_ushort(l1) << 16);
}

// ---------------------------------------------------------------------------
// Persistent node-projection GEMM on HMMA (mma.sync bf16, 3x split).
// Tile: 128 nodes x 256 outputs, K=128. 8 warps in 2(M) x 4(N) grid, 64x64/warp.
// ---------------------------------------------------------------------------
__global__ void __launch_bounds__(256, 1)
node_mma_kernel(const float* __restrict__ feat,
                const float* __restrict__ W1,
                const float* __restrict__ b1,
                int n_nodes, int n_tiles) {
    extern __shared__ __nv_bfloat16 smem[];
    const uint32_t sbase = smem_u32(smem);
    const int tid = threadIdx.x;
    const int wid = tid >> 5;
    const int lane = tid & 31;

    // ---- Convert W1 -> B_hi/B_lo once per CTA. B[o][k] = W1[o&127][(o>>7)*128+k] ----
    #pragma unroll 4
    for (int it = 0; it < 64; ++it) {
        int g = tid + it * 256;              // pair index 0..16383
        int o = g >> 6;
        int cp = g & 63;                     // k-pair
        float2 v = *reinterpret_cast<const float2*>(
            W1 + (size_t)(o & 127) * 256 + (o >> 7) * 128 + cp * 2);
        uint32_t eoff = (uint32_t)o * BSTRIDE + cp * 2;
        *reinterpret_cast<uint32_t*>(smem + OFF_BHI + eoff) = pack_hi(v.x, v.y);
        *reinterpret_cast<uint32_t*>(smem + OFF_BLO + eoff) = pack_lo(v.x, v.y);
    }

    const int m0 = (wid & 1) * 64;
    const int n0 = (wid >> 1) * 64;
    // ldmatrix per-lane address components
    const int a_row = (lane & 15);
    const int a_col = (lane >> 4) * 8;
    const int b_row = ((lane >> 4) << 3) + (lane & 7);
    const int b_col = ((lane >> 3) & 1) * 8;
    // epilogue per-lane position
    const int tr = lane >> 2;
    const int tc = (lane & 3) * 2;

    for (int tile = blockIdx.x; tile < n_tiles; tile += gridDim.x) {
        __syncthreads();   // previous tile's smem reads complete

        // ---- Load + convert A tile -> A_hi/A_lo ----
        const int node0 = tile * 128;
        #pragma unroll 4
        for (int it = 0; it < 32; ++it) {
            int g = tid + it * 256;          // pair index 0..8191
            int row = g >> 6;
            int cp = g & 63;
            int node = node0 + row;
            float2 v = make_float2(0.f, 0.f);
            if (node < n_nodes)
                v = *reinterpret_cast<const float2*>(feat + (size_t)node * 128 + cp * 2);
            uint32_t eoff = (uint32_t)row * BSTRIDE + cp * 2;
            *reinterpret_cast<uint32_t*>(smem + OFF_AHI + eoff) = pack_hi(v.x, v.y);
            *reinterpret_cast<uint32_t*>(smem + OFF_ALO + eoff) = pack_lo(v.x, v.y);
        }
        __syncthreads();

        // ---- MMA mainloop ----
        float d[4][8][4];
        #pragma unroll
        for (int mt = 0; mt < 4; ++mt)
            #pragma unroll
            for (int nt = 0; nt < 8; ++nt)
                #pragma unroll
                for (int j = 0; j < 4; ++j) d[mt][nt][j] = 0.f;

        #pragma unroll
        for (int ks = 0; ks < 8; ++ks) {
            const int k = ks * 16;
            uint32_t ah[4][4], al[4][4], bh[4][4], bl[4][4];
            #pragma unroll
            for (int mt = 0; mt < 4; ++mt) {
                uint32_t eoff = (uint32_t)(m0 + mt * 16 + a_row) * BSTRIDE + k + a_col;
                ldsm_x4(ah[mt], sbase + (OFF_AHI + eoff) * 2);
                ldsm_x4(al[mt], sbase + (OFF_ALO + eoff) * 2);
            }
            #pragma unroll
            for (int np = 0; np < 4; ++np) {
                uint32_t eoff = (uint32_t)(n0 + np * 16 + b_row) * BSTRIDE + k + b_col;
                ldsm_x4(bh[np], sbase + (OFF_BHI + eoff) * 2);
                ldsm_x4(bl[np], sbase + (OFF_BLO + eoff) * 2);
            }
            #pragma unroll
            for (int mt = 0; mt < 4; ++mt)
                #pragma unroll
                for (int nt = 0; nt < 8; ++nt) {
                    const uint32_t* bhp = &bh[nt >> 1][(nt & 1) * 2];
                    const uint32_t* blp = &bl[nt >> 1][(nt & 1) * 2];
                    mma_bf16(d[mt][nt], ah[mt], bhp);
                    mma_bf16(d[mt][nt], ah[mt], blp);
                    mma_bf16(d[mt][nt], al[mt], bhp);
                }
        }

        // ---- Epilogue: fold b1 into P columns (col < 128), write g_R ----
        #pragma unroll
        for (int nt = 0; nt < 8; ++nt) {
            int col = n0 + nt * 8 + tc;
            float2 bias = make_float2(0.f, 0.f);
            if (col < 128) bias = *reinterpret_cast<const float2*>(b1 + col);
            #pragma unroll
            for (int mt = 0; mt < 4; ++mt) {
                int row0 = m0 + mt * 16 + tr;
                int na = node0 + row0, nb = na + 8;
                if (na < n_nodes) {
                    float2 o = make_float2(d[mt][nt][0] + bias.x, d[mt][nt][1] + bias.y);
                    *reinterpret_cast<float2*>(g_R + (size_t)na * 256 + col) = o;
                }
                if (nb < n_nodes) {
                    float2 o = make_float2(d[mt][nt][2] + bias.x, d[mt][nt][3] + bias.y);
                    *reinterpret_cast<float2*>(g_R + (size_t)nb * 256 + col) = o;
                }
            }
        }
    }
}

// ---------------------------------------------------------------------------
// Kernel 2: per-edge score, 8 edges/warp (proven R3 version, LTS-cap bound).
// score[e] = W2 . relu(P[src] + Q[dst]) + b2   (b1 already inside P)
// ---------------------------------------------------------------------------
#define EPW 8
__global__ void edge_score_kernel(const int* __restrict__ src,
                                  const int* __restrict__ dst,
                                  const float* __restrict__ W2,
                                  const float* __restrict__ b2,
                                  float* __restrict__ out,
                                  int n_edges) {
    int warp = (int)((blockIdx.x * (unsigned)blockDim.x + threadIdx.x) >> 5);
    int lane = threadIdx.x & 31;
    int e0 = warp * EPW;
    if (e0 >= n_edges) return;

    const float4 w = __ldg(reinterpret_cast<const float4*>(W2) + lane);

    int si[EPW], di[EPW];
    #pragma unroll
    for (int j = 0; j < EPW; ++j) {
        int e = min(e0 + j, n_edges - 1);
        si[j] = __ldg(src + e);
        di[j] = __ldg(dst + e);
    }

    float4 p[EPW], q[EPW];
    #pragma unroll
    for (int j = 0; j < EPW; ++j)
        p[j] = *reinterpret_cast<const float4*>(g_R + (size_t)si[j] * 256 + lane * 4);
    #pragma unroll
    for (int j = 0; j < EPW; ++j)
        q[j] = *reinterpret_cast<const float4*>(g_R + (size_t)di[j] * 256 + 128 + lane * 4);

    float v[EPW];
    #pragma unroll
    for (int j = 0; j < EPW; ++j) {
        v[j] = fmaxf(p[j].x + q[j].x, 0.f) * w.x
             + fmaxf(p[j].y + q[j].y, 0.f) * w.y
             + fmaxf(p[j].z + q[j].z, 0.f) * w.z
             + fmaxf(p[j].w + q[j].w, 0.f) * w.w;
    }

    #pragma unroll
    for (int off = 16; off; off >>= 1)
        #pragma unroll
        for (int j = 0; j < EPW; ++j)
            v[j] += __shfl_xor_sync(0xffffffffu, v[j], off);

    if (lane == 0) {
        float bias = __ldg(b2);
        if (e0 + EPW <= n_edges) {
            float4 o0 = make_float4(v[0] + bias, v[1] + bias, v[2] + bias, v[3] + bias);
            float4 o1 = make_float4(v[4] + bias, v[5] + bias, v[6] + bias, v[7] + bias);
            *reinterpret_cast<float4*>(out + e0) = o0;
            *reinterpret_cast<float4*>(out + e0 + 4) = o1;
        } else {
            for (int j = 0; j < n_edges - e0; ++j) out[e0 + j] = v[j] + bias;
        }
    }
}

// ---------------------------------------------------------------------------
// kernel_launch — graph-capturable, allocation-free.
// Inputs: feature[f32 N*128], src[i32 E], dst[i32 E],
//         W1[f32 128*256], b1[f32 128], W2[f32 128], b2[f32 1]
// ---------------------------------------------------------------------------
extern "C" void kernel_launch(void* const* d_in, const int* in_sizes, int n_in,
                              void* d_out, int out_size) {
    const float* feat = (const float*)d_in[0];
    const int*   src  = (const int*)d_in[1];
    const int*   dst  = (const int*)d_in[2];
    const float* W1   = (const float*)d_in[3];
    const float* b1   = (const float*)d_in[4];
    const float* W2   = (const float*)d_in[5];
    const float* b2   = (const float*)d_in[6];
    float*       out  = (float*)d_out;

    int n_nodes = in_sizes[0] / FEAT;
    int n_edges = in_sizes[1];
    int n_tiles = (n_nodes + 127) / 128;

    const int smem_bytes = SMEM_ELEMS * 2;   // 208896 B
    cudaFuncSetAttribute(node_mma_kernel,
                         cudaFuncAttributeMaxDynamicSharedMemorySize, smem_bytes);

    int grid = n_tiles < 148 ? n_tiles : 148;
    node_mma_kernel<<<grid, 256, smem_bytes>>>(feat, W1, b1, n_nodes, n_tiles);

    int warps = (n_edges + EPW - 1) / EPW;
    int blocks = (warps * 32 + 255) / 256;
    edge_score_kernel<<<blocks, 256>>>(src, dst, W2, b2, out, n_edges);
}

// round 6
// speedup vs baseline: 2.0004x; 1.1198x over previous
#include <cuda_runtime.h>
#include <cuda_bf16.h>
#include <cuda_fp16.h>
#include <cstdint>

#define NODES_MAX 100032
#define FEAT 128
#define BSTRIDE 136   // bf16 elems per smem row (128 + 8 pad -> 272B, ldmatrix conflict-free)

// Per-node projections, fp16 storage (halves LTS bytes; 51MB -> L2-resident):
// g_H[n][o<128] = feat[n]@W1[o][0:128].T + b1[o],  g_H[n][128+j] = feat[n]@W1[j][128:256].T
__device__ __half g_H[(size_t)NODES_MAX * 256];

// smem offsets in bf16 elements
#define OFF_AHI 0
#define OFF_ALO (128 * BSTRIDE)
#define OFF_BHI (256 * BSTRIDE)
#define OFF_BLO (512 * BSTRIDE)
#define SMEM_ELEMS (768 * BSTRIDE)              // 104448 elems = 208896 B

__device__ __forceinline__ uint32_t smem_u32(const void* p) {
    uint32_t a;
    asm("{ .reg .u64 t; cvta.to.shared.u64 t, %1; cvt.u32.u64 %0, t; }" : "=r"(a) : "l"(p));
    return a;
}
__device__ __forceinline__ void ldsm_x4(uint32_t* r, uint32_t addr) {
    asm volatile("ldmatrix.sync.aligned.m8n8.x4.shared.b16 {%0,%1,%2,%3}, [%4];"
                 : "=r"(r[0]), "=r"(r[1]), "=r"(r[2]), "=r"(r[3]) : "r"(addr));
}
__device__ __forceinline__ void mma_bf16(float* d, const uint32_t* a, const uint32_t* b) {
    asm volatile("mma.sync.aligned.m16n8k16.row.col.f32.bf16.bf16.f32 "
                 "{%0,%1,%2,%3}, {%4,%5,%6,%7}, {%8,%9}, {%0,%1,%2,%3};"
                 : "+f"(d[0]), "+f"(d[1]), "+f"(d[2]), "+f"(d[3])
                 : "r"(a[0]), "r"(a[1]), "r"(a[2]), "r"(a[3]), "r"(b[0]), "r"(b[1]));
}
__device__ __forceinline__ uint32_t pack_hi(float x, float y) {
    __nv_bfloat16 h0 = __float2bfloat16(x), h1 = __float2bfloat16(y);
    return (uint32_t)__bfloat16_as_ushort(h0) | ((uint32_t)__bfloat16_as_ushort(h1) << 16);
}
__device__ __forceinline__ uint32_t pack_lo(float x, float y) {
    __nv_bfloat16 h0 = __float2bfloat16(x), h1 = __float2bfloat16(y);
    __nv_bfloat16 l0 = __float2bfloat16(x - __bfloat162float(h0));
    __nv_bfloat16 l1 = __float2bfloat16(y - __bfloat162float(h1));
    return (uint32_t)__bfloat16_as_ushort(l0) | ((uint32_t)__bfloat16_as_ushort(l1) << 16);
}

// ---------------------------------------------------------------------------
// Persistent node-projection GEMM on HMMA (mma.sync bf16, 3x split).
// Tile: 128 nodes x 256 outputs, K=128. 8 warps in 2(M) x 4(N) grid, 64x64/warp.
// ---------------------------------------------------------------------------
__global__ void __launch_bounds__(256, 1)
node_mma_kernel(const float* __restrict__ feat,
                const float* __restrict__ W1,
                const float* __restrict__ b1,
                int n_nodes, int n_tiles) {
    extern __shared__ __nv_bfloat16 smem[];
    const uint32_t sbase = smem_u32(smem);
    const int tid = threadIdx.x;
    const int wid = tid >> 5;
    const int lane = tid & 31;

    // ---- Convert W1 -> B_hi/B_lo once per CTA. B[o][k] = W1[o&127][(o>>7)*128+k] ----
    #pragma unroll 4
    for (int it = 0; it < 64; ++it) {
        int g = tid + it * 256;              // pair index 0..16383
        int o = g >> 6;
        int cp = g & 63;                     // k-pair
        float2 v = *reinterpret_cast<const float2*>(
            W1 + (size_t)(o & 127) * 256 + (o >> 7) * 128 + cp * 2);
        uint32_t eoff = (uint32_t)o * BSTRIDE + cp * 2;
        *reinterpret_cast<uint32_t*>(smem + OFF_BHI + eoff) = pack_hi(v.x, v.y);
        *reinterpret_cast<uint32_t*>(smem + OFF_BLO + eoff) = pack_lo(v.x, v.y);
    }

    const int m0 = (wid & 1) * 64;
    const int n0 = (wid >> 1) * 64;
    // ldmatrix per-lane address components
    const int a_row = (lane & 15);
    const int a_col = (lane >> 4) * 8;
    const int b_row = ((lane >> 4) << 3) + (lane & 7);
    const int b_col = ((lane >> 3) & 1) * 8;
    // epilogue per-lane position
    const int tr = lane >> 2;
    const int tc = (lane & 3) * 2;

    for (int tile = blockIdx.x; tile < n_tiles; tile += gridDim.x) {
        __syncthreads();   // previous tile's smem reads complete

        // ---- Load + convert A tile -> A_hi/A_lo ----
        const int node0 = tile * 128;
        #pragma unroll 4
        for (int it = 0; it < 32; ++it) {
            int g = tid + it * 256;          // pair index 0..8191
            int row = g >> 6;
            int cp = g & 63;
            int node = node0 + row;
            float2 v = make_float2(0.f, 0.f);
            if (node < n_nodes)
                v = *reinterpret_cast<const float2*>(feat + (size_t)node * 128 + cp * 2);
            uint32_t eoff = (uint32_t)row * BSTRIDE + cp * 2;
            *reinterpret_cast<uint32_t*>(smem + OFF_AHI + eoff) = pack_hi(v.x, v.y);
            *reinterpret_cast<uint32_t*>(smem + OFF_ALO + eoff) = pack_lo(v.x, v.y);
        }
        __syncthreads();

        // ---- MMA mainloop ----
        float d[4][8][4];
        #pragma unroll
        for (int mt = 0; mt < 4; ++mt)
            #pragma unroll
            for (int nt = 0; nt < 8; ++nt)
                #pragma unroll
                for (int j = 0; j < 4; ++j) d[mt][nt][j] = 0.f;

        #pragma unroll
        for (int ks = 0; ks < 8; ++ks) {
            const int k = ks * 16;
            uint32_t ah[4][4], al[4][4], bh[4][4], bl[4][4];
            #pragma unroll
            for (int mt = 0; mt < 4; ++mt) {
                uint32_t eoff = (uint32_t)(m0 + mt * 16 + a_row) * BSTRIDE + k + a_col;
                ldsm_x4(ah[mt], sbase + (OFF_AHI + eoff) * 2);
                ldsm_x4(al[mt], sbase + (OFF_ALO + eoff) * 2);
            }
            #pragma unroll
            for (int np = 0; np < 4; ++np) {
                uint32_t eoff = (uint32_t)(n0 + np * 16 + b_row) * BSTRIDE + k + b_col;
                ldsm_x4(bh[np], sbase + (OFF_BHI + eoff) * 2);
                ldsm_x4(bl[np], sbase + (OFF_BLO + eoff) * 2);
            }
            #pragma unroll
            for (int mt = 0; mt < 4; ++mt)
                #pragma unroll
                for (int nt = 0; nt < 8; ++nt) {
                    const uint32_t* bhp = &bh[nt >> 1][(nt & 1) * 2];
                    const uint32_t* blp = &bl[nt >> 1][(nt & 1) * 2];
                    mma_bf16(d[mt][nt], ah[mt], bhp);
                    mma_bf16(d[mt][nt], ah[mt], blp);
                    mma_bf16(d[mt][nt], al[mt], bhp);
                }
        }

        // ---- Epilogue: fold b1 into P columns (col < 128), write g_H (fp16) ----
        #pragma unroll
        for (int nt = 0; nt < 8; ++nt) {
            int col = n0 + nt * 8 + tc;
            float2 bias = make_float2(0.f, 0.f);
            if (col < 128) bias = *reinterpret_cast<const float2*>(b1 + col);
            #pragma unroll
            for (int mt = 0; mt < 4; ++mt) {
                int row0 = m0 + mt * 16 + tr;
                int na = node0 + row0, nb = na + 8;
                if (na < n_nodes) {
                    __half2 o = __floats2half2_rn(d[mt][nt][0] + bias.x, d[mt][nt][1] + bias.y);
                    *reinterpret_cast<__half2*>(g_H + (size_t)na * 256 + col) = o;
                }
                if (nb < n_nodes) {
                    __half2 o = __floats2half2_rn(d[mt][nt][2] + bias.x, d[mt][nt][3] + bias.y);
                    *reinterpret_cast<__half2*>(g_H + (size_t)nb * 256 + col) = o;
                }
            }
        }
    }
}

// ---------------------------------------------------------------------------
// Kernel 2: per-edge score, 8 edges/warp, fp16 gathers (256B per row-half).
// score[e] = W2 . relu(P[src] + Q[dst]) + b2   (b1 already inside P)
// ---------------------------------------------------------------------------
#define EPW 8
__global__ void edge_score_kernel(const int* __restrict__ src,
                                  const int* __restrict__ dst,
                                  const float* __restrict__ W2,
                                  const float* __restrict__ b2,
                                  float* __restrict__ out,
                                  int n_edges) {
    int warp = (int)((blockIdx.x * (unsigned)blockDim.x + threadIdx.x) >> 5);
    int lane = threadIdx.x & 31;
    int e0 = warp * EPW;
    if (e0 >= n_edges) return;

    const float4 w = __ldg(reinterpret_cast<const float4*>(W2) + lane);

    int si[EPW], di[EPW];
    #pragma unroll
    for (int j = 0; j < EPW; ++j) {
        int e = min(e0 + j, n_edges - 1);
        si[j] = __ldg(src + e);
        di[j] = __ldg(dst + e);
    }

    // 4 fp16 channels per lane = one 8B load per row-half
    uint2 pu[EPW], qu[EPW];
    #pragma unroll
    for (int j = 0; j < EPW; ++j)
        pu[j] = *reinterpret_cast<const uint2*>(g_H + (size_t)si[j] * 256 + lane * 4);
    #pragma unroll
    for (int j = 0; j < EPW; ++j)
        qu[j] = *reinterpret_cast<const uint2*>(g_H + (size_t)di[j] * 256 + 128 + lane * 4);

    float v[EPW];
    #pragma unroll
    for (int j = 0; j < EPW; ++j) {
        float2 p0 = __half22float2(*reinterpret_cast<const __half2*>(&pu[j].x));
        float2 p1 = __half22float2(*reinterpret_cast<const __half2*>(&pu[j].y));
        float2 q0 = __half22float2(*reinterpret_cast<const __half2*>(&qu[j].x));
        float2 q1 = __half22float2(*reinterpret_cast<const __half2*>(&qu[j].y));
        v[j] = fmaxf(p0.x + q0.x, 0.f) * w.x
             + fmaxf(p0.y + q0.y, 0.f) * w.y
             + fmaxf(p1.x + q1.x, 0.f) * w.z
             + fmaxf(p1.y + q1.y, 0.f) * w.w;
    }

    #pragma unroll
    for (int off = 16; off; off >>= 1)
        #pragma unroll
        for (int j = 0; j < EPW; ++j)
            v[j] += __shfl_xor_sync(0xffffffffu, v[j], off);

    if (lane == 0) {
        float bias = __ldg(b2);
        if (e0 + EPW <= n_edges) {
            float4 o0 = make_float4(v[0] + bias, v[1] + bias, v[2] + bias, v[3] + bias);
            float4 o1 = make_float4(v[4] + bias, v[5] + bias, v[6] + bias, v[7] + bias);
            *reinterpret_cast<float4*>(out + e0) = o0;
            *reinterpret_cast<float4*>(out + e0 + 4) = o1;
        } else {
            for (int j = 0; j < n_edges - e0; ++j) out[e0 + j] = v[j] + bias;
        }
    }
}

// ---------------------------------------------------------------------------
// kernel_launch — graph-capturable, allocation-free.
// Inputs: feature[f32 N*128], src[i32 E], dst[i32 E],
//         W1[f32 128*256], b1[f32 128], W2[f32 128], b2[f32 1]
// ---------------------------------------------------------------------------
extern "C" void kernel_launch(void* const* d_in, const int* in_sizes, int n_in,
                              void* d_out, int out_size) {
    const float* feat = (const float*)d_in[0];
    const int*   src  = (const int*)d_in[1];
    const int*   dst  = (const int*)d_in[2];
    const float* W1   = (const float*)d_in[3];
    const float* b1   = (const float*)d_in[4];
    const float* W2   = (const float*)d_in[5];
    const float* b2   = (const float*)d_in[6];
    float*       out  = (float*)d_out;

    int n_nodes = in_sizes[0] / FEAT;
    int n_edges = in_sizes[1];
    int n_tiles = (n_nodes + 127) / 128;

    const int smem_bytes = SMEM_ELEMS * 2;   // 208896 B
    cudaFuncSetAttribute(node_mma_kernel,
                         cudaFuncAttributeMaxDynamicSharedMemorySize, smem_bytes);

    int grid = n_tiles < 148 ? n_tiles : 148;
    node_mma_kernel<<<grid, 256, smem_bytes>>>(feat, W1, b1, n_nodes, n_tiles);

    int warps = (n_edges + EPW - 1) / EPW;
    int blocks = (warps * 32 + 255) / 256;
    edge_score_kernel<<<blocks, 256>>>(src, dst, W2, b2, out, n_edges);
}

// round 7
// speedup vs baseline: 2.7844x; 1.3919x over previous
#include <cuda_runtime.h>
#include <cuda_fp16.h>
#include <cstdint>

#define NODES_MAX 100032
#define FEAT 128
#define BSTRIDE 136   // fp16 elems per smem row (272B: ldmatrix conflict-free, 16B-aligned)

// Per-node projections, fp16: g_H[n][o<128] = feat[n]@W1[o][0:128].T + b1[o]
//                             g_H[n][128+j] = feat[n]@W1[j][128:256].T
__device__ __half g_H[(size_t)NODES_MAX * 256];

// smem offsets in half elements: A double-buffered, B single
#define OFF_A0 0
#define OFF_A1 (128 * BSTRIDE)
#define OFF_B  (256 * BSTRIDE)
#define SMEM_HALVES (512 * BSTRIDE)     // 69632 halves = 139264 B

__device__ __forceinline__ uint32_t smem_u32(const void* p) {
    uint32_t a;
    asm("{ .reg .u64 t; cvta.to.shared.u64 t, %1; cvt.u32.u64 %0, t; }" : "=r"(a) : "l"(p));
    return a;
}
__device__ __forceinline__ void ldsm_x4(uint32_t* r, uint32_t addr) {
    asm volatile("ldmatrix.sync.aligned.m8n8.x4.shared.b16 {%0,%1,%2,%3}, [%4];"
                 : "=r"(r[0]), "=r"(r[1]), "=r"(r[2]), "=r"(r[3]) : "r"(addr));
}
__device__ __forceinline__ void mma_f16(float* d, const uint32_t* a, const uint32_t* b) {
    asm volatile("mma.sync.aligned.m16n8k16.row.col.f32.f16.f16.f32 "
                 "{%0,%1,%2,%3}, {%4,%5,%6,%7}, {%8,%9}, {%0,%1,%2,%3};"
                 : "+f"(d[0]), "+f"(d[1]), "+f"(d[2]), "+f"(d[3])
                 : "r"(a[0]), "r"(a[1]), "r"(a[2]), "r"(a[3]), "r"(b[0]), "r"(b[1]));
}

// ---- A tile staging: prefetch fp32 into regs, convert+store later ----
__device__ __forceinline__ void prefetch_A(const float* __restrict__ feat, int node0,
                                           int n_nodes, int tid, float4* pf) {
    const float4* f4 = reinterpret_cast<const float4*>(feat);
    #pragma unroll
    for (int it = 0; it < 16; ++it) {
        int g = tid + it * 256;          // float4 idx 0..4095 (128 rows x 32)
        int row = g >> 5, c4 = g & 31;
        int node = node0 + row;
        pf[it] = (node < n_nodes) ? f4[(size_t)node * 32 + c4]
                                  : make_float4(0.f, 0.f, 0.f, 0.f);
    }
}
__device__ __forceinline__ void store_A(__half* smem, uint32_t offA, int tid, const float4* pf) {
    #pragma unroll
    for (int it = 0; it < 16; ++it) {
        int g = tid + it * 256;
        int row = g >> 5, c4 = g & 31;
        __half2 h0 = __floats2half2_rn(pf[it].x, pf[it].y);
        __half2 h1 = __floats2half2_rn(pf[it].z, pf[it].w);
        uint2 u;
        u.x = *reinterpret_cast<uint32_t*>(&h0);
        u.y = *reinterpret_cast<uint32_t*>(&h1);
        *reinterpret_cast<uint2*>(smem + offA + (uint32_t)row * BSTRIDE + c4 * 4) = u;
    }
}

// ---------------------------------------------------------------------------
// Persistent node-projection GEMM, single-fp16 HMMA, A double-buffered.
// Tile: 128 nodes x 256 outputs, K=128. 8 warps 2(M) x 4(N), 64x64/warp.
// ---------------------------------------------------------------------------
__global__ void __launch_bounds__(256, 1)
node_mma_kernel(const float* __restrict__ feat,
                const float* __restrict__ W1,
                const float* __restrict__ b1,
                int n_nodes, int n_tiles) {
    extern __shared__ __half smem[];
    const uint32_t sbase = smem_u32(smem);
    const int tid = threadIdx.x;
    const int wid = tid >> 5;
    const int lane = tid & 31;

    float4 pf[16];
    prefetch_A(feat, blockIdx.x * 128, n_nodes, tid, pf);   // first tile, early

    // ---- Convert W1 -> B (fp16) once. B[o][k] = W1[o&127][(o>>7)*128+k] ----
    #pragma unroll 4
    for (int it = 0; it < 32; ++it) {
        int g = tid + it * 256;              // float4 idx 0..8191 (256 rows x 32)
        int o = g >> 5, c4 = g & 31;
        float4 v = *reinterpret_cast<const float4*>(
            W1 + (size_t)(o & 127) * 256 + (o >> 7) * 128 + c4 * 4);
        __half2 h0 = __floats2half2_rn(v.x, v.y);
        __half2 h1 = __floats2half2_rn(v.z, v.w);
        uint2 u;
        u.x = *reinterpret_cast<uint32_t*>(&h0);
        u.y = *reinterpret_cast<uint32_t*>(&h1);
        *reinterpret_cast<uint2*>(smem + OFF_B + (uint32_t)o * BSTRIDE + c4 * 4) = u;
    }

    store_A(smem, OFF_A0, tid, pf);
    __syncthreads();

    const int m0 = (wid & 1) * 64;
    const int n0 = (wid >> 1) * 64;
    const int a_row = (lane & 15);
    const int a_col = (lane >> 4) * 8;
    const int b_row = ((lane >> 4) << 3) + (lane & 7);
    const int b_col = ((lane >> 3) & 1) * 8;
    const int tr = lane >> 2;
    const int tc = (lane & 3) * 2;

    int p = 0;
    for (int tile = blockIdx.x; tile < n_tiles; tile += gridDim.x) {
        const int next = tile + gridDim.x;
        if (next < n_tiles) prefetch_A(feat, next * 128, n_nodes, tid, pf);

        const uint32_t offA = p ? OFF_A1 : OFF_A0;
        const int node0 = tile * 128;

        float d[4][8][4];
        #pragma unroll
        for (int mt = 0; mt < 4; ++mt)
            #pragma unroll
            for (int nt = 0; nt < 8; ++nt)
                #pragma unroll
                for (int j = 0; j < 4; ++j) d[mt][nt][j] = 0.f;

        #pragma unroll
        for (int ks = 0; ks < 8; ++ks) {
            const int k = ks * 16;
            uint32_t af[4][4], bf[4][4];
            #pragma unroll
            for (int mt = 0; mt < 4; ++mt)
                ldsm_x4(af[mt], sbase + (offA + (uint32_t)(m0 + mt * 16 + a_row) * BSTRIDE + k + a_col) * 2);
            #pragma unroll
            for (int np = 0; np < 4; ++np)
                ldsm_x4(bf[np], sbase + (OFF_B + (uint32_t)(n0 + np * 16 + b_row) * BSTRIDE + k + b_col) * 2);
            #pragma unroll
            for (int mt = 0; mt < 4; ++mt)
                #pragma unroll
                for (int nt = 0; nt < 8; ++nt)
                    mma_f16(d[mt][nt], af[mt], &bf[nt >> 1][(nt & 1) * 2]);
        }

        // ---- Epilogue: fold b1 into P columns (col < 128), write g_H (fp16) ----
        #pragma unroll
        for (int nt = 0; nt < 8; ++nt) {
            int col = n0 + nt * 8 + tc;
            float2 bias = make_float2(0.f, 0.f);
            if (col < 128) bias = *reinterpret_cast<const float2*>(b1 + col);
            #pragma unroll
            for (int mt = 0; mt < 4; ++mt) {
                int row0 = m0 + mt * 16 + tr;
                int na = node0 + row0, nb = na + 8;
                if (na < n_nodes) {
                    __half2 o = __floats2half2_rn(d[mt][nt][0] + bias.x, d[mt][nt][1] + bias.y);
                    *reinterpret_cast<__half2*>(g_H + (size_t)na * 256 + col) = o;
                }
                if (nb < n_nodes) {
                    __half2 o = __floats2half2_rn(d[mt][nt][2] + bias.x, d[mt][nt][3] + bias.y);
                    *reinterpret_cast<__half2*>(g_H + (size_t)nb * 256 + col) = o;
                }
            }
        }

        if (next < n_tiles) store_A(smem, p ? OFF_A0 : OFF_A1, tid, pf);
        __syncthreads();
        p ^= 1;
    }
}

// ---------------------------------------------------------------------------
// Kernel 2: per-edge score, 8 edges/warp, fp16 gathers, lane-specialized
// multi-reduction (9 shfl instead of 40).
// ---------------------------------------------------------------------------
#define EPW 8
__global__ void edge_score_kernel(const int* __restrict__ src,
                                  const int* __restrict__ dst,
                                  const float* __restrict__ W2,
                                  const float* __restrict__ b2,
                                  float* __restrict__ out,
                                  int n_edges) {
    int warp = (int)((blockIdx.x * (unsigned)blockDim.x + threadIdx.x) >> 5);
    int lane = threadIdx.x & 31;
    int e0 = warp * EPW;
    if (e0 >= n_edges) return;

    const float4 w = __ldg(reinterpret_cast<const float4*>(W2) + lane);

    int si[EPW], di[EPW];
    #pragma unroll
    for (int j = 0; j < EPW; ++j) {
        int e = min(e0 + j, n_edges - 1);
        si[j] = __ldg(src + e);
        di[j] = __ldg(dst + e);
    }

    uint2 pu[EPW], qu[EPW];
    #pragma unroll
    for (int j = 0; j < EPW; ++j)
        pu[j] = *reinterpret_cast<const uint2*>(g_H + (size_t)si[j] * 256 + lane * 4);
    #pragma unroll
    for (int j = 0; j < EPW; ++j)
        qu[j] = *reinterpret_cast<const uint2*>(g_H + (size_t)di[j] * 256 + 128 + lane * 4);

    float v[EPW];
    #pragma unroll
    for (int j = 0; j < EPW; ++j) {
        float2 p0 = __half22float2(*reinterpret_cast<const __half2*>(&pu[j].x));
        float2 p1 = __half22float2(*reinterpret_cast<const __half2*>(&pu[j].y));
        float2 q0 = __half22float2(*reinterpret_cast<const __half2*>(&qu[j].x));
        float2 q1 = __half22float2(*reinterpret_cast<const __half2*>(&qu[j].y));
        v[j] = fmaxf(p0.x + q0.x, 0.f) * w.x
             + fmaxf(p0.y + q0.y, 0.f) * w.y
             + fmaxf(p1.x + q1.x, 0.f) * w.z
             + fmaxf(p1.y + q1.y, 0.f) * w.w;
    }

    // Lane-specialized reduction: 8 sums over 32 lanes in 9 shuffles.
    const unsigned FULL = 0xffffffffu;
    bool h16 = lane & 16;
    float a0 = (h16 ? v[4] : v[0]) + __shfl_xor_sync(FULL, h16 ? v[0] : v[4], 16);
    float a1 = (h16 ? v[5] : v[1]) + __shfl_xor_sync(FULL, h16 ? v[1] : v[5], 16);
    float a2 = (h16 ? v[6] : v[2]) + __shfl_xor_sync(FULL, h16 ? v[2] : v[6], 16);
    float a3 = (h16 ? v[7] : v[3]) + __shfl_xor_sync(FULL, h16 ? v[3] : v[7], 16);
    bool h8 = lane & 8;
    float b0 = (h8 ? a2 : a0) + __shfl_xor_sync(FULL, h8 ? a0 : a2, 8);
    float b1v = (h8 ? a3 : a1) + __shfl_xor_sync(FULL, h8 ? a1 : a3, 8);
    bool h4 = lane & 4;
    float c = (h4 ? b1v : b0) + __shfl_xor_sync(FULL, h4 ? b0 : b1v, 4);
    c += __shfl_xor_sync(FULL, c, 2);
    c += __shfl_xor_sync(FULL, c, 1);
    // lane holds edge (lane>>2): bits {4,8,16} selected edge bits {2,1,0}... mapping:
    // edge = (h4?1:0) + (h8?2:0) + (h16?4:0) = lane>>2 for lanes 4e.
    int e = lane >> 2;
    if ((lane & 3) == 0 && e0 + e < n_edges)
        out[e0 + e] = c + __ldg(b2);
}

// ---------------------------------------------------------------------------
// kernel_launch — graph-capturable, allocation-free.
// Inputs: feature[f32 N*128], src[i32 E], dst[i32 E],
//         W1[f32 128*256], b1[f32 128], W2[f32 128], b2[f32 1]
// ---------------------------------------------------------------------------
extern "C" void kernel_launch(void* const* d_in, const int* in_sizes, int n_in,
                              void* d_out, int out_size) {
    const float* feat = (const float*)d_in[0];
    const int*   src  = (const int*)d_in[1];
    const int*   dst  = (const int*)d_in[2];
    const float* W1   = (const float*)d_in[3];
    const float* b1   = (const float*)d_in[4];
    const float* W2   = (const float*)d_in[5];
    const float* b2   = (const float*)d_in[6];
    float*       out  = (float*)d_out;

    int n_nodes = in_sizes[0] / FEAT;
    int n_edges = in_sizes[1];
    int n_tiles = (n_nodes + 127) / 128;

    const int smem_bytes = SMEM_HALVES * 2;   // 139264 B
    cudaFuncSetAttribute(node_mma_kernel,
                         cudaFuncAttributeMaxDynamicSharedMemorySize, smem_bytes);

    int grid = n_tiles < 148 ? n_tiles : 148;
    node_mma_kernel<<<grid, 256, smem_bytes>>>(feat, W1, b1, n_nodes, n_tiles);

    int warps = (n_edges + EPW - 1) / EPW;
    int blocks = (warps * 32 + 255) / 256;
    edge_score_kernel<<<blocks, 256>>>(src, dst, W2, b2, out, n_edges);
}

// round 8
// speedup vs baseline: 4.3636x; 1.5672x over previous
#include <cuda_runtime.h>
#include <cuda_fp16.h>
#include <cstdint>

#define NODES_MAX 100032
#define FEAT 128
#define BSTRIDE 136   // fp16 elems per smem row (272B: ldmatrix conflict-free, 16B-aligned)
#define BLOCK 512

// Per-node projections, fp16: g_H[n][o<128] = feat[n]@W1[o][0:128].T + b1[o]
//                             g_H[n][128+j] = feat[n]@W1[j][128:256].T
__device__ __half g_H[(size_t)NODES_MAX * 256];

// smem offsets in half elements: A double-buffered, B single
#define OFF_A0 0
#define OFF_A1 (128 * BSTRIDE)
#define OFF_B  (256 * BSTRIDE)
#define SMEM_HALVES (512 * BSTRIDE)     // 69632 halves = 139264 B

__device__ __forceinline__ uint32_t smem_u32(const void* p) {
    uint32_t a;
    asm("{ .reg .u64 t; cvta.to.shared.u64 t, %1; cvt.u32.u64 %0, t; }" : "=r"(a) : "l"(p));
    return a;
}
__device__ __forceinline__ void ldsm_x4(uint32_t* r, uint32_t addr) {
    asm volatile("ldmatrix.sync.aligned.m8n8.x4.shared.b16 {%0,%1,%2,%3}, [%4];"
                 : "=r"(r[0]), "=r"(r[1]), "=r"(r[2]), "=r"(r[3]) : "r"(addr));
}
__device__ __forceinline__ void mma_f16(float* d, const uint32_t* a, const uint32_t* b) {
    asm volatile("mma.sync.aligned.m16n8k16.row.col.f32.f16.f16.f32 "
                 "{%0,%1,%2,%3}, {%4,%5,%6,%7}, {%8,%9}, {%0,%1,%2,%3};"
                 : "+f"(d[0]), "+f"(d[1]), "+f"(d[2]), "+f"(d[3])
                 : "r"(a[0]), "r"(a[1]), "r"(a[2]), "r"(a[3]), "r"(b[0]), "r"(b[1]));
}

// ---- A tile staging: prefetch fp32 into regs, convert+store later ----
__device__ __forceinline__ void prefetch_A(const float* __restrict__ feat, int node0,
                                           int n_nodes, int tid, float4* pf) {
    const float4* f4 = reinterpret_cast<const float4*>(feat);
    #pragma unroll
    for (int it = 0; it < 8; ++it) {
        int g = tid + it * BLOCK;        // float4 idx 0..4095 (128 rows x 32)
        int row = g >> 5, c4 = g & 31;
        int node = node0 + row;
        pf[it] = (node < n_nodes) ? f4[(size_t)node * 32 + c4]
                                  : make_float4(0.f, 0.f, 0.f, 0.f);
    }
}
__device__ __forceinline__ void store_A(__half* smem, uint32_t offA, int tid, const float4* pf) {
    #pragma unroll
    for (int it = 0; it < 8; ++it) {
        int g = tid + it * BLOCK;
        int row = g >> 5, c4 = g & 31;
        __half2 h0 = __floats2half2_rn(pf[it].x, pf[it].y);
        __half2 h1 = __floats2half2_rn(pf[it].z, pf[it].w);
        uint2 u;
        u.x = *reinterpret_cast<uint32_t*>(&h0);
        u.y = *reinterpret_cast<uint32_t*>(&h1);
        *reinterpret_cast<uint2*>(smem + offA + (uint32_t)row * BSTRIDE + c4 * 4) = u;
    }
}

// ---------------------------------------------------------------------------
// Persistent node-projection GEMM, fp16 HMMA, A double-buffered.
// Tile: 128 nodes x 256 outputs, K=128. 16 warps in 4(M) x 4(N), 32x64/warp.
// ---------------------------------------------------------------------------
__global__ void __launch_bounds__(BLOCK, 1)
node_mma_kernel(const float* __restrict__ feat,
                const float* __restrict__ W1,
                const float* __restrict__ b1,
                int n_nodes, int n_tiles) {
    extern __shared__ __half smem[];
    const uint32_t sbase = smem_u32(smem);
    const int tid = threadIdx.x;
    const int wid = tid >> 5;
    const int lane = tid & 31;

    float4 pf[8];
    prefetch_A(feat, blockIdx.x * 128, n_nodes, tid, pf);   // first tile, early

    // ---- Convert W1 -> B (fp16) once. B[o][k] = W1[o&127][(o>>7)*128+k] ----
    #pragma unroll 4
    for (int it = 0; it < 16; ++it) {
        int g = tid + it * BLOCK;            // float4 idx 0..8191 (256 rows x 32)
        int o = g >> 5, c4 = g & 31;
        float4 v = *reinterpret_cast<const float4*>(
            W1 + (size_t)(o & 127) * 256 + (o >> 7) * 128 + c4 * 4);
        __half2 h0 = __floats2half2_rn(v.x, v.y);
        __half2 h1 = __floats2half2_rn(v.z, v.w);
        uint2 u;
        u.x = *reinterpret_cast<uint32_t*>(&h0);
        u.y = *reinterpret_cast<uint32_t*>(&h1);
        *reinterpret_cast<uint2*>(smem + OFF_B + (uint32_t)o * BSTRIDE + c4 * 4) = u;
    }

    store_A(smem, OFF_A0, tid, pf);
    __syncthreads();

    const int m0 = (wid & 3) * 32;
    const int n0 = (wid >> 2) * 64;
    const int a_row = (lane & 15);
    const int a_col = (lane >> 4) * 8;
    const int b_row = ((lane >> 4) << 3) + (lane & 7);
    const int b_col = ((lane >> 3) & 1) * 8;
    const int tr = lane >> 2;
    const int tc = (lane & 3) * 2;

    int p = 0;
    for (int tile = blockIdx.x; tile < n_tiles; tile += gridDim.x) {
        const int next = tile + gridDim.x;
        if (next < n_tiles) prefetch_A(feat, next * 128, n_nodes, tid, pf);

        const uint32_t offA = p ? OFF_A1 : OFF_A0;
        const int node0 = tile * 128;

        float d[2][8][4];
        #pragma unroll
        for (int mt = 0; mt < 2; ++mt)
            #pragma unroll
            for (int nt = 0; nt < 8; ++nt)
                #pragma unroll
                for (int j = 0; j < 4; ++j) d[mt][nt][j] = 0.f;

        #pragma unroll
        for (int ks = 0; ks < 8; ++ks) {
            const int k = ks * 16;
            uint32_t af[2][4], bf[4][4];
            #pragma unroll
            for (int mt = 0; mt < 2; ++mt)
                ldsm_x4(af[mt], sbase + (offA + (uint32_t)(m0 + mt * 16 + a_row) * BSTRIDE + k + a_col) * 2);
            #pragma unroll
            for (int np = 0; np < 4; ++np)
                ldsm_x4(bf[np], sbase + (OFF_B + (uint32_t)(n0 + np * 16 + b_row) * BSTRIDE + k + b_col) * 2);
            #pragma unroll
            for (int mt = 0; mt < 2; ++mt)
                #pragma unroll
                for (int nt = 0; nt < 8; ++nt)
                    mma_f16(d[mt][nt], af[mt], &bf[nt >> 1][(nt & 1) * 2]);
        }

        // ---- Epilogue: fold b1 into P columns (col < 128), write g_H (fp16) ----
        #pragma unroll
        for (int nt = 0; nt < 8; ++nt) {
            int col = n0 + nt * 8 + tc;
            float2 bias = make_float2(0.f, 0.f);
            if (col < 128) bias = *reinterpret_cast<const float2*>(b1 + col);
            #pragma unroll
            for (int mt = 0; mt < 2; ++mt) {
                int row0 = m0 + mt * 16 + tr;
                int na = node0 + row0, nb = na + 8;
                if (na < n_nodes) {
                    __half2 o = __floats2half2_rn(d[mt][nt][0] + bias.x, d[mt][nt][1] + bias.y);
                    *reinterpret_cast<__half2*>(g_H + (size_t)na * 256 + col) = o;
                }
                if (nb < n_nodes) {
                    __half2 o = __floats2half2_rn(d[mt][nt][2] + bias.x, d[mt][nt][3] + bias.y);
                    *reinterpret_cast<__half2*>(g_H + (size_t)nb * 256 + col) = o;
                }
            }
        }

        if (next < n_tiles) store_A(smem, p ? OFF_A0 : OFF_A1, tid, pf);
        __syncthreads();
        p ^= 1;
    }
}

// ---------------------------------------------------------------------------
// Kernel 2: per-edge score, 8 edges/warp. Add+ReLU in half2, dot in fp32.
// 32-bit byte offsets into g_H (table < 2^31 bytes).
// ---------------------------------------------------------------------------
#define EPW 8
__global__ void edge_score_kernel(const int* __restrict__ src,
                                  const int* __restrict__ dst,
                                  const float* __restrict__ W2,
                                  const float* __restrict__ b2,
                                  float* __restrict__ out,
                                  int n_edges) {
    int warp = (int)((blockIdx.x * (unsigned)blockDim.x + threadIdx.x) >> 5);
    int lane = threadIdx.x & 31;
    int e0 = warp * EPW;
    if (e0 >= n_edges) return;

    const float4 w = __ldg(reinterpret_cast<const float4*>(W2) + lane);
    const char* base = reinterpret_cast<const char*>(g_H);
    const uint32_t lb = (uint32_t)lane * 8u;

    uint32_t po[EPW], qo[EPW];
    #pragma unroll
    for (int j = 0; j < EPW; ++j) {
        int e = min(e0 + j, n_edges - 1);
        po[j] = (uint32_t)__ldg(src + e) * 512u + lb;
        qo[j] = (uint32_t)__ldg(dst + e) * 512u + 256u + lb;
    }

    uint2 pu[EPW], qu[EPW];
    #pragma unroll
    for (int j = 0; j < EPW; ++j)
        pu[j] = *reinterpret_cast<const uint2*>(base + po[j]);
    #pragma unroll
    for (int j = 0; j < EPW; ++j)
        qu[j] = *reinterpret_cast<const uint2*>(base + qo[j]);

    const __half2 z2 = __float2half2_rn(0.f);
    float v[EPW];
    #pragma unroll
    for (int j = 0; j < EPW; ++j) {
        __half2 s0 = __hmax2(__hadd2(*reinterpret_cast<const __half2*>(&pu[j].x),
                                     *reinterpret_cast<const __half2*>(&qu[j].x)), z2);
        __half2 s1 = __hmax2(__hadd2(*reinterpret_cast<const __half2*>(&pu[j].y),
                                     *reinterpret_cast<const __half2*>(&qu[j].y)), z2);
        float2 f0 = __half22float2(s0);
        float2 f1 = __half22float2(s1);
        v[j] = fmaf(f0.x, w.x, fmaf(f0.y, w.y, fmaf(f1.x, w.z, f1.y * w.w)));
    }

    // Lane-specialized reduction: 8 sums over 32 lanes in 9 shuffles.
    const unsigned FULL = 0xffffffffu;
    bool h16 = lane & 16;
    float a0 = (h16 ? v[4] : v[0]) + __shfl_xor_sync(FULL, h16 ? v[0] : v[4], 16);
    float a1 = (h16 ? v[5] : v[1]) + __shfl_xor_sync(FULL, h16 ? v[1] : v[5], 16);
    float a2 = (h16 ? v[6] : v[2]) + __shfl_xor_sync(FULL, h16 ? v[2] : v[6], 16);
    float a3 = (h16 ? v[7] : v[3]) + __shfl_xor_sync(FULL, h16 ? v[3] : v[7], 16);
    bool h8 = lane & 8;
    float b0 = (h8 ? a2 : a0) + __shfl_xor_sync(FULL, h8 ? a0 : a2, 8);
    float b1v = (h8 ? a3 : a1) + __shfl_xor_sync(FULL, h8 ? a1 : a3, 8);
    bool h4 = lane & 4;
    float c = (h4 ? b1v : b0) + __shfl_xor_sync(FULL, h4 ? b0 : b1v, 4);
    c += __shfl_xor_sync(FULL, c, 2);
    c += __shfl_xor_sync(FULL, c, 1);
    int e = lane >> 2;
    if ((lane & 3) == 0 && e0 + e < n_edges)
        out[e0 + e] = c + __ldg(b2);
}

// ---------------------------------------------------------------------------
// kernel_launch — graph-capturable, allocation-free.
// Inputs: feature[f32 N*128], src[i32 E], dst[i32 E],
//         W1[f32 128*256], b1[f32 128], W2[f32 128], b2[f32 1]
// ---------------------------------------------------------------------------
extern "C" void kernel_launch(void* const* d_in, const int* in_sizes, int n_in,
                              void* d_out, int out_size) {
    const float* feat = (const float*)d_in[0];
    const int*   src  = (const int*)d_in[1];
    const int*   dst  = (const int*)d_in[2];
    const float* W1   = (const float*)d_in[3];
    const float* b1   = (const float*)d_in[4];
    const float* W2   = (const float*)d_in[5];
    const float* b2   = (const float*)d_in[6];
    float*       out  = (float*)d_out;

    int n_nodes = in_sizes[0] / FEAT;
    int n_edges = in_sizes[1];
    int n_tiles = (n_nodes + 127) / 128;

    const int smem_bytes = SMEM_HALVES * 2;   // 139264 B
    cudaFuncSetAttribute(node_mma_kernel,
                         cudaFuncAttributeMaxDynamicSharedMemorySize, smem_bytes);

    int grid = n_tiles < 148 ? n_tiles : 148;
    node_mma_kernel<<<grid, BLOCK, smem_bytes>>>(feat, W1, b1, n_nodes, n_tiles);

    int warps = (n_edges + EPW - 1) / EPW;
    int blocks = (warps * 32 + 255) / 256;
    edge_score_kernel<<<blocks, 256>>>(src, dst, W2, b2, out, n_edges);
}

// round 9
// speedup vs baseline: 4.4260x; 1.0143x over previous
#include <cuda_runtime.h>
#include <cuda_fp16.h>
#include <cstdint>

#define NODES_MAX 100032
#define FEAT 128
#define BSTRIDE 136    // fp16 elems per smem A/B row (272B: ldmatrix conflict-free)
#define DSTRIDE 264    // fp16 elems per smem D-stage row (528B: 4-bank rotation/row)
#define BLOCK 512

// Per-node projections, fp16: g_H[n][o<128] = feat[n]@W1[o][0:128].T + b1[o]
//                             g_H[n][128+j] = feat[n]@W1[j][128:256].T
__device__ __half g_H[(size_t)NODES_MAX * 256];

// smem offsets in half elements: A double-buffered, B single, D staging
#define OFF_A0 0
#define OFF_A1 (128 * BSTRIDE)
#define OFF_B  (256 * BSTRIDE)
#define OFF_D  (512 * BSTRIDE)
#define SMEM_HALVES (512 * BSTRIDE + 128 * DSTRIDE)   // 103424 halves = 206848 B

__device__ __forceinline__ uint32_t smem_u32(const void* p) {
    uint32_t a;
    asm("{ .reg .u64 t; cvta.to.shared.u64 t, %1; cvt.u32.u64 %0, t; }" : "=r"(a) : "l"(p));
    return a;
}
__device__ __forceinline__ void ldsm_x4(uint32_t* r, uint32_t addr) {
    asm volatile("ldmatrix.sync.aligned.m8n8.x4.shared.b16 {%0,%1,%2,%3}, [%4];"
                 : "=r"(r[0]), "=r"(r[1]), "=r"(r[2]), "=r"(r[3]) : "r"(addr));
}
__device__ __forceinline__ void mma_f16(float* d, const uint32_t* a, const uint32_t* b) {
    asm volatile("mma.sync.aligned.m16n8k16.row.col.f32.f16.f16.f32 "
                 "{%0,%1,%2,%3}, {%4,%5,%6,%7}, {%8,%9}, {%0,%1,%2,%3};"
                 : "+f"(d[0]), "+f"(d[1]), "+f"(d[2]), "+f"(d[3])
                 : "r"(a[0]), "r"(a[1]), "r"(a[2]), "r"(a[3]), "r"(b[0]), "r"(b[1]));
}

// ---- A tile staging: prefetch fp32 into regs, convert+store later ----
__device__ __forceinline__ void prefetch_A(const float* __restrict__ feat, int node0,
                                           int n_nodes, int tid, float4* pf) {
    const float4* f4 = reinterpret_cast<const float4*>(feat);
    #pragma unroll
    for (int it = 0; it < 8; ++it) {
        int g = tid + it * BLOCK;        // float4 idx 0..4095 (128 rows x 32)
        int row = g >> 5, c4 = g & 31;
        int node = node0 + row;
        pf[it] = (node < n_nodes) ? f4[(size_t)node * 32 + c4]
                                  : make_float4(0.f, 0.f, 0.f, 0.f);
    }
}
__device__ __forceinline__ void store_A(__half* smem, uint32_t offA, int tid, const float4* pf) {
    #pragma unroll
    for (int it = 0; it < 8; ++it) {
        int g = tid + it * BLOCK;
        int row = g >> 5, c4 = g & 31;
        __half2 h0 = __floats2half2_rn(pf[it].x, pf[it].y);
        __half2 h1 = __floats2half2_rn(pf[it].z, pf[it].w);
        uint2 u;
        u.x = *reinterpret_cast<uint32_t*>(&h0);
        u.y = *reinterpret_cast<uint32_t*>(&h1);
        *reinterpret_cast<uint2*>(smem + offA + (uint32_t)row * BSTRIDE + c4 * 4) = u;
    }
}

// ---------------------------------------------------------------------------
// Persistent node-projection GEMM, fp16 HMMA, A double-buffered,
// smem-staged coalesced epilogue.
// Tile: 128 nodes x 256 outputs, K=128. 16 warps in 4(M) x 4(N), 32x64/warp.
// ---------------------------------------------------------------------------
__global__ void __launch_bounds__(BLOCK, 1)
node_mma_kernel(const float* __restrict__ feat,
                const float* __restrict__ W1,
                const float* __restrict__ b1,
                int n_nodes, int n_tiles) {
    extern __shared__ __half smem[];
    const uint32_t sbase = smem_u32(smem);
    const int tid = threadIdx.x;
    const int wid = tid >> 5;
    const int lane = tid & 31;

    float4 pf[8];
    prefetch_A(feat, blockIdx.x * 128, n_nodes, tid, pf);   // first tile, early

    // ---- Convert W1 -> B (fp16) once. B[o][k] = W1[o&127][(o>>7)*128+k] ----
    #pragma unroll 4
    for (int it = 0; it < 16; ++it) {
        int g = tid + it * BLOCK;            // float4 idx 0..8191 (256 rows x 32)
        int o = g >> 5, c4 = g & 31;
        float4 v = *reinterpret_cast<const float4*>(
            W1 + (size_t)(o & 127) * 256 + (o >> 7) * 128 + c4 * 4);
        __half2 h0 = __floats2half2_rn(v.x, v.y);
        __half2 h1 = __floats2half2_rn(v.z, v.w);
        uint2 u;
        u.x = *reinterpret_cast<uint32_t*>(&h0);
        u.y = *reinterpret_cast<uint32_t*>(&h1);
        *reinterpret_cast<uint2*>(smem + OFF_B + (uint32_t)o * BSTRIDE + c4 * 4) = u;
    }

    store_A(smem, OFF_A0, tid, pf);
    __syncthreads();

    const int m0 = (wid & 3) * 32;
    const int n0 = (wid >> 2) * 64;
    const int a_row = (lane & 15);
    const int a_col = (lane >> 4) * 8;
    const int b_row = ((lane >> 4) << 3) + (lane & 7);
    const int b_col = ((lane >> 3) & 1) * 8;
    const int tr = lane >> 2;
    const int tc = (lane & 3) * 2;

    int p = 0;
    for (int tile = blockIdx.x; tile < n_tiles; tile += gridDim.x) {
        const int next = tile + gridDim.x;
        if (next < n_tiles) prefetch_A(feat, next * 128, n_nodes, tid, pf);

        const uint32_t offA = p ? OFF_A1 : OFF_A0;
        const int node0 = tile * 128;

        float d[2][8][4];
        #pragma unroll
        for (int mt = 0; mt < 2; ++mt)
            #pragma unroll
            for (int nt = 0; nt < 8; ++nt)
                #pragma unroll
                for (int j = 0; j < 4; ++j) d[mt][nt][j] = 0.f;

        #pragma unroll
        for (int ks = 0; ks < 8; ++ks) {
            const int k = ks * 16;
            uint32_t af[2][4], bf[4][4];
            #pragma unroll
            for (int mt = 0; mt < 2; ++mt)
                ldsm_x4(af[mt], sbase + (offA + (uint32_t)(m0 + mt * 16 + a_row) * BSTRIDE + k + a_col) * 2);
            #pragma unroll
            for (int np = 0; np < 4; ++np)
                ldsm_x4(bf[np], sbase + (OFF_B + (uint32_t)(n0 + np * 16 + b_row) * BSTRIDE + k + b_col) * 2);
            #pragma unroll
            for (int mt = 0; mt < 2; ++mt)
                #pragma unroll
                for (int nt = 0; nt < 8; ++nt)
                    mma_f16(d[mt][nt], af[mt], &bf[nt >> 1][(nt & 1) * 2]);
        }

        // ---- Epilogue 1: bias + cvt, STS fragments into D stage (conflict-free) ----
        #pragma unroll
        for (int nt = 0; nt < 8; ++nt) {
            int col = n0 + nt * 8 + tc;
            float2 bias = make_float2(0.f, 0.f);
            if (col < 128) bias = *reinterpret_cast<const float2*>(b1 + col);
            #pragma unroll
            for (int mt = 0; mt < 2; ++mt) {
                int ra = m0 + mt * 16 + tr;          // local rows
                __half2 oa = __floats2half2_rn(d[mt][nt][0] + bias.x, d[mt][nt][1] + bias.y);
                __half2 ob = __floats2half2_rn(d[mt][nt][2] + bias.x, d[mt][nt][3] + bias.y);
                *reinterpret_cast<__half2*>(smem + OFF_D + (uint32_t)ra * DSTRIDE + col) = oa;
                *reinterpret_cast<__half2*>(smem + OFF_D + (uint32_t)(ra + 8) * DSTRIDE + col) = ob;
            }
        }
        __syncthreads();

        // ---- Epilogue 2: coalesced copy stage -> g_H (LDS.128 + STG.128) ----
        #pragma unroll
        for (int it = 0; it < 8; ++it) {
            int g = tid + it * BLOCK;        // uint4 idx 0..4095 (128 rows x 32)
            int row = g >> 5, c16 = g & 31;
            int node = node0 + row;
            if (node < n_nodes) {
                uint4 v = *reinterpret_cast<const uint4*>(smem + OFF_D + (uint32_t)row * DSTRIDE + c16 * 8);
                *reinterpret_cast<uint4*>(g_H + (size_t)node * 256 + c16 * 8) = v;
            }
        }

        if (next < n_tiles) store_A(smem, p ? OFF_A0 : OFF_A1, tid, pf);
        __syncthreads();
        p ^= 1;
    }
}

// ---------------------------------------------------------------------------
// Kernel 2: per-edge score, 8 edges/warp. Vectorized int4 index loads,
// half2 add+relu, fp32 dot, lane-specialized 9-shuffle reduction.
// ---------------------------------------------------------------------------
#define EPW 8
__global__ void edge_score_kernel(const int* __restrict__ src,
                                  const int* __restrict__ dst,
                                  const float* __restrict__ W2,
                                  const float* __restrict__ b2,
                                  float* __restrict__ out,
                                  int n_edges) {
    int warp = (int)((blockIdx.x * (unsigned)blockDim.x + threadIdx.x) >> 5);
    int lane = threadIdx.x & 31;
    int e0 = warp * EPW;
    if (e0 >= n_edges) return;

    const float4 w = __ldg(reinterpret_cast<const float4*>(W2) + lane);
    const char* base = reinterpret_cast<const char*>(g_H);
    const uint32_t lb = (uint32_t)lane * 8u;

    int si[EPW], di[EPW];
    if (e0 + EPW <= n_edges) {
        // e0 is 8-aligned -> 16B-aligned int4 loads
        int4 sa = __ldg(reinterpret_cast<const int4*>(src + e0));
        int4 sb = __ldg(reinterpret_cast<const int4*>(src + e0 + 4));
        int4 da = __ldg(reinterpret_cast<const int4*>(dst + e0));
        int4 db = __ldg(reinterpret_cast<const int4*>(dst + e0 + 4));
        si[0] = sa.x; si[1] = sa.y; si[2] = sa.z; si[3] = sa.w;
        si[4] = sb.x; si[5] = sb.y; si[6] = sb.z; si[7] = sb.w;
        di[0] = da.x; di[1] = da.y; di[2] = da.z; di[3] = da.w;
        di[4] = db.x; di[5] = db.y; di[6] = db.z; di[7] = db.w;
    } else {
        #pragma unroll
        for (int j = 0; j < EPW; ++j) {
            int e = min(e0 + j, n_edges - 1);
            si[j] = __ldg(src + e);
            di[j] = __ldg(dst + e);
        }
    }

    uint2 pu[EPW], qu[EPW];
    #pragma unroll
    for (int j = 0; j < EPW; ++j)
        pu[j] = *reinterpret_cast<const uint2*>(base + ((uint32_t)si[j] * 512u + lb));
    #pragma unroll
    for (int j = 0; j < EPW; ++j)
        qu[j] = *reinterpret_cast<const uint2*>(base + ((uint32_t)di[j] * 512u + 256u + lb));

    const __half2 z2 = __float2half2_rn(0.f);
    float v[EPW];
    #pragma unroll
    for (int j = 0; j < EPW; ++j) {
        __half2 s0 = __hmax2(__hadd2(*reinterpret_cast<const __half2*>(&pu[j].x),
                                     *reinterpret_cast<const __half2*>(&qu[j].x)), z2);
        __half2 s1 = __hmax2(__hadd2(*reinterpret_cast<const __half2*>(&pu[j].y),
                                     *reinterpret_cast<const __half2*>(&qu[j].y)), z2);
        float2 f0 = __half22float2(s0);
        float2 f1 = __half22float2(s1);
        v[j] = fmaf(f0.x, w.x, fmaf(f0.y, w.y, fmaf(f1.x, w.z, f1.y * w.w)));
    }

    // Lane-specialized reduction: 8 sums over 32 lanes in 9 shuffles.
    const unsigned FULL = 0xffffffffu;
    bool h16 = lane & 16;
    float a0 = (h16 ? v[4] : v[0]) + __shfl_xor_sync(FULL, h16 ? v[0] : v[4], 16);
    float a1 = (h16 ? v[5] : v[1]) + __shfl_xor_sync(FULL, h16 ? v[1] : v[5], 16);
    float a2 = (h16 ? v[6] : v[2]) + __shfl_xor_sync(FULL, h16 ? v[2] : v[6], 16);
    float a3 = (h16 ? v[7] : v[3]) + __shfl_xor_sync(FULL, h16 ? v[3] : v[7], 16);
    bool h8 = lane & 8;
    float b0 = (h8 ? a2 : a0) + __shfl_xor_sync(FULL, h8 ? a0 : a2, 8);
    float b1v = (h8 ? a3 : a1) + __shfl_xor_sync(FULL, h8 ? a1 : a3, 8);
    bool h4 = lane & 4;
    float c = (h4 ? b1v : b0) + __shfl_xor_sync(FULL, h4 ? b0 : b1v, 4);
    c += __shfl_xor_sync(FULL, c, 2);
    c += __shfl_xor_sync(FULL, c, 1);
    int e = lane >> 2;
    if ((lane & 3) == 0 && e0 + e < n_edges)
        out[e0 + e] = c + __ldg(b2);
}

// ---------------------------------------------------------------------------
// kernel_launch — graph-capturable, allocation-free.
// Inputs: feature[f32 N*128], src[i32 E], dst[i32 E],
//         W1[f32 128*256], b1[f32 128], W2[f32 128], b2[f32 1]
// ---------------------------------------------------------------------------
extern "C" void kernel_launch(void* const* d_in, const int* in_sizes, int n_in,
                              void* d_out, int out_size) {
    const float* feat = (const float*)d_in[0];
    const int*   src  = (const int*)d_in[1];
    const int*   dst  = (const int*)d_in[2];
    const float* W1   = (const float*)d_in[3];
    const float* b1   = (const float*)d_in[4];
    const float* W2   = (const float*)d_in[5];
    const float* b2   = (const float*)d_in[6];
    float*       out  = (float*)d_out;

    int n_nodes = in_sizes[0] / FEAT;
    int n_edges = in_sizes[1];
    int n_tiles = (n_nodes + 127) / 128;

    const int smem_bytes = SMEM_HALVES * 2;   // 206848 B
    cudaFuncSetAttribute(node_mma_kernel,
                         cudaFuncAttributeMaxDynamicSharedMemorySize, smem_bytes);

    int grid = n_tiles < 148 ? n_tiles : 148;
    node_mma_kernel<<<grid, BLOCK, smem_bytes>>>(feat, W1, b1, n_nodes, n_tiles);

    int warps = (n_edges + EPW - 1) / EPW;
    int blocks = (warps * 32 + 255) / 256;
    edge_score_kernel<<<blocks, 256>>>(src, dst, W2, b2, out, n_edges);
}